// round 1
// baseline (speedup 1.0000x reference)
#include <cuda_runtime.h>

#define W 224
#define WW (W * W)                 // 50176
#define F4_PER (WW / 4)            // 12544 float4 per sample
#define F4_PER_ROW (W / 4)         // 56 (a float4 never crosses a row)
#define MAXB 1024

// Scratch (device globals — no allocation allowed)
__device__ float2 g_xy[MAXB];
__device__ double g_acc;

struct AMax { float m; int cnt; int si; int sj; };

__device__ __forceinline__ void amax_merge(AMax& a, float m, int cnt, int si, int sj) {
    if (m > a.m) { a.m = m; a.cnt = cnt; a.si = si; a.sj = sj; }
    else if (m == a.m) { a.cnt += cnt; a.si += si; a.sj += sj; }
}

// ---------------------------------------------------------------------------
// Kernel 1: per-sample argmax centroid of target. One block per sample.
// ---------------------------------------------------------------------------
__global__ void k_argmax(const float* __restrict__ tgt) {
    const int b = blockIdx.x;
    const float4* t4 = reinterpret_cast<const float4*>(tgt) + (size_t)b * F4_PER;

    AMax a; a.m = -3.0e38f; a.cnt = 0; a.si = 0; a.sj = 0;

    for (int p = threadIdx.x; p < F4_PER; p += blockDim.x) {
        float4 v = t4[p];
        int i  = p / F4_PER_ROW;
        int j0 = (p - i * F4_PER_ROW) * 4;
        amax_merge(a, v.x, 1, i, j0 + 0);
        amax_merge(a, v.y, 1, i, j0 + 1);
        amax_merge(a, v.z, 1, i, j0 + 2);
        amax_merge(a, v.w, 1, i, j0 + 3);
    }

    // warp reduce
    #pragma unroll
    for (int o = 16; o > 0; o >>= 1) {
        float m  = __shfl_down_sync(0xffffffffu, a.m,  o);
        int   c  = __shfl_down_sync(0xffffffffu, a.cnt, o);
        int   si = __shfl_down_sync(0xffffffffu, a.si, o);
        int   sj = __shfl_down_sync(0xffffffffu, a.sj, o);
        amax_merge(a, m, c, si, sj);
    }

    __shared__ AMax sm[8];
    const int wid = threadIdx.x >> 5, lid = threadIdx.x & 31;
    if (lid == 0) sm[wid] = a;
    __syncthreads();

    if (threadIdx.x == 0) {
        AMax r = sm[0];
        const int nw = blockDim.x >> 5;
        for (int w = 1; w < nw; w++) amax_merge(r, sm[w].m, sm[w].cnt, sm[w].si, sm[w].sj);
        float inv = 1.0f / (float)r.cnt;
        g_xy[b] = make_float2((float)r.si * inv, (float)r.sj * inv);
        if (b == 0) g_acc = 0.0;   // re-zero accumulator every graph replay
    }
}

// ---------------------------------------------------------------------------
// Kernel 2: weighted BCE partial sums. grid = (F4_PER/256, B), 256 thr.
// Each thread handles exactly one float4 of (input, target).
// ---------------------------------------------------------------------------
__global__ void k_loss(const float* __restrict__ inp, const float* __restrict__ tgt) {
    const int b = blockIdx.y;
    const int p = blockIdx.x * blockDim.x + threadIdx.x;   // f4 index in sample
    const float2 xy = g_xy[b];

    const size_t base = (size_t)b * F4_PER + p;
    float4 pv = reinterpret_cast<const float4*>(inp)[base];
    float4 tv = reinterpret_cast<const float4*>(tgt)[base];

    const int i  = p / F4_PER_ROW;
    const int j0 = (p - i * F4_PER_ROW) * 4;
    const float di  = (float)i - xy.x;
    const float di2 = di * di;

    float pe[4] = {pv.x, pv.y, pv.z, pv.w};
    float te[4] = {tv.x, tv.y, tv.z, tv.w};

    float s = 0.0f;
    #pragma unroll
    for (int k = 0; k < 4; k++) {
        float dj  = (float)(j0 + k) - xy.y;
        float wgt = __fdividef((float)W, sqrtf(fmaf(dj, dj, di2)) + 1.0f);
        float lp  = fmaxf(__logf(pe[k]),        -100.0f);
        float lq  = fmaxf(__logf(1.0f - pe[k]), -100.0f);
        float bce = -(te[k] * lp + (1.0f - te[k]) * lq);
        s += wgt * bce;
    }

    // warp reduce
    #pragma unroll
    for (int o = 16; o > 0; o >>= 1)
        s += __shfl_down_sync(0xffffffffu, s, o);

    __shared__ float sw[8];
    const int wid = threadIdx.x >> 5, lid = threadIdx.x & 31;
    if (lid == 0) sw[wid] = s;
    __syncthreads();

    if (threadIdx.x == 0) {
        float bs = sw[0];
        const int nw = blockDim.x >> 5;
        for (int w = 1; w < nw; w++) bs += sw[w];
        atomicAdd(&g_acc, (double)bs);
    }
}

// ---------------------------------------------------------------------------
// Kernel 3: finalize mean.
// ---------------------------------------------------------------------------
__global__ void k_final(float* __restrict__ out, double invn) {
    out[0] = (float)(g_acc * invn);
}

extern "C" void kernel_launch(void* const* d_in, const int* in_sizes, int n_in,
                              void* d_out, int out_size) {
    const float* inp = (const float*)d_in[0];
    const float* tgt = (const float*)d_in[1];
    float* out = (float*)d_out;

    const int n = in_sizes[0];
    const int B = n / WW;     // 256

    k_argmax<<<B, 256>>>(tgt);
    dim3 grid2(F4_PER / 256, B);   // (49, 256)
    k_loss<<<grid2, 256>>>(inp, tgt);
    k_final<<<1, 1>>>(out, 1.0 / (double)((size_t)B * WW));
}

// round 2
// speedup vs baseline: 1.2381x; 1.2381x over previous
#include <cuda_runtime.h>

#define W 224
#define WW (W * W)                 // 50176
#define F4_PER (WW / 4)            // 12544 float4 per sample
#define F4_PER_ROW (W / 4)         // 56
#define NSAMP 256
#define F4_TOTAL (NSAMP * F4_PER)  // 3,211,264

// Scratch (device globals — no allocation allowed)
__device__ float2 g_xy[NSAMP];
__device__ double g_acc;

// ---------------------------------------------------------------------------
// Kernel 1: per-sample argmax centroid. One block (1024 thr) per sample.
// Pass A: branch-free max (4 independent fmaxf accumulators, streaming).
// Pass B: re-scan (L2-hot) counting ties, with a cheap skip test per float4.
// ---------------------------------------------------------------------------
__global__ __launch_bounds__(1024) void k_argmax(const float* __restrict__ tgt) {
    const int b = blockIdx.x;
    const int tid = threadIdx.x;
    const float4* __restrict__ t4 = reinterpret_cast<const float4*>(tgt) + (size_t)b * F4_PER;

    // ---- Pass A: block max, branch-free ----
    float m0 = -3.0e38f, m1 = m0, m2 = m0, m3 = m0;
    for (int p = tid; p < F4_PER; p += 1024) {
        float4 v = t4[p];
        m0 = fmaxf(m0, v.x);
        m1 = fmaxf(m1, v.y);
        m2 = fmaxf(m2, v.z);
        m3 = fmaxf(m3, v.w);
    }
    float m = fmaxf(fmaxf(m0, m1), fmaxf(m2, m3));
    #pragma unroll
    for (int o = 16; o > 0; o >>= 1)
        m = fmaxf(m, __shfl_xor_sync(0xffffffffu, m, o));

    __shared__ float smax[32];
    __shared__ float sM;
    const int wid = tid >> 5, lid = tid & 31;
    if (lid == 0) smax[wid] = m;
    __syncthreads();
    if (tid == 0) {
        float bm = smax[0];
        #pragma unroll
        for (int w = 1; w < 32; w++) bm = fmaxf(bm, smax[w]);
        sM = bm;
    }
    __syncthreads();
    const float M = sM;

    // ---- Pass B: count ties + index sums (reads hit L2/L1) ----
    int cnt = 0, si = 0, sj = 0;
    for (int p = tid; p < F4_PER; p += 1024) {
        float4 v = t4[p];
        float mm = fmaxf(fmaxf(v.x, v.y), fmaxf(v.z, v.w));
        if (mm == M) {                     // ~1 in 12544 iterations
            int i  = p / F4_PER_ROW;
            int j0 = (p - i * F4_PER_ROW) * 4;
            if (v.x == M) { cnt++; si += i; sj += j0;     }
            if (v.y == M) { cnt++; si += i; sj += j0 + 1; }
            if (v.z == M) { cnt++; si += i; sj += j0 + 2; }
            if (v.w == M) { cnt++; si += i; sj += j0 + 3; }
        }
    }
    #pragma unroll
    for (int o = 16; o > 0; o >>= 1) {
        cnt += __shfl_xor_sync(0xffffffffu, cnt, o);
        si  += __shfl_xor_sync(0xffffffffu, si,  o);
        sj  += __shfl_xor_sync(0xffffffffu, sj,  o);
    }

    __shared__ int scnt[32], ssi[32], ssj[32];
    if (lid == 0) { scnt[wid] = cnt; ssi[wid] = si; ssj[wid] = sj; }
    __syncthreads();
    if (tid == 0) {
        int c = 0, a = 0, d = 0;
        #pragma unroll
        for (int w = 0; w < 32; w++) { c += scnt[w]; a += ssi[w]; d += ssj[w]; }
        float inv = 1.0f / (float)c;
        g_xy[b] = make_float2((float)a * inv, (float)d * inv);
        if (b == 0) g_acc = 0.0;           // re-zero accumulator each replay
    }
}

// ---------------------------------------------------------------------------
// Kernel 2: weighted BCE partial sums.
// grid = F4_TOTAL / (256*4) = 3136 blocks, 256 thr, 4 coalesced float4/thread.
// ---------------------------------------------------------------------------
__global__ __launch_bounds__(256) void k_loss(const float* __restrict__ inp,
                                              const float* __restrict__ tgt) {
    const float4* __restrict__ p4 = reinterpret_cast<const float4*>(inp);
    const float4* __restrict__ t4 = reinterpret_cast<const float4*>(tgt);

    float s = 0.0f;
    #pragma unroll
    for (int k = 0; k < 4; k++) {
        const int p = blockIdx.x * 1024 + k * 256 + threadIdx.x;   // global f4 idx
        float4 pv = p4[p];
        float4 tv = t4[p];

        const int b = p / F4_PER;
        const int r = p - b * F4_PER;
        const int i  = r / F4_PER_ROW;
        const int j0 = (r - i * F4_PER_ROW) * 4;

        const float2 xy = g_xy[b];
        const float di  = (float)i - xy.x;
        const float di2 = di * di;

        float pe[4] = {pv.x, pv.y, pv.z, pv.w};
        float te[4] = {tv.x, tv.y, tv.z, tv.w};
        #pragma unroll
        for (int e = 0; e < 4; e++) {
            float dj  = (float)(j0 + e) - xy.y;
            float wgt = __fdividef((float)W, sqrtf(fmaf(dj, dj, di2)) + 1.0f);
            float lp  = fmaxf(__logf(pe[e]),        -100.0f);
            float lq  = fmaxf(__logf(1.0f - pe[e]), -100.0f);
            s += wgt * (-(te[e] * lp + (1.0f - te[e]) * lq));
        }
    }

    #pragma unroll
    for (int o = 16; o > 0; o >>= 1)
        s += __shfl_xor_sync(0xffffffffu, s, o);

    __shared__ float sw[8];
    const int wid = threadIdx.x >> 5, lid = threadIdx.x & 31;
    if (lid == 0) sw[wid] = s;
    __syncthreads();
    if (threadIdx.x == 0) {
        float bs = sw[0];
        #pragma unroll
        for (int w = 1; w < 8; w++) bs += sw[w];
        atomicAdd(&g_acc, (double)bs);
    }
}

// ---------------------------------------------------------------------------
// Kernel 3: finalize mean.
// ---------------------------------------------------------------------------
__global__ void k_final(float* __restrict__ out, double invn) {
    out[0] = (float)(g_acc * invn);
}

extern "C" void kernel_launch(void* const* d_in, const int* in_sizes, int n_in,
                              void* d_out, int out_size) {
    const float* inp = (const float*)d_in[0];
    const float* tgt = (const float*)d_in[1];
    float* out = (float*)d_out;

    k_argmax<<<NSAMP, 1024>>>(tgt);
    k_loss<<<F4_TOTAL / 1024, 256>>>(inp, tgt);
    k_final<<<1, 1>>>(out, 1.0 / (double)((size_t)NSAMP * WW));
}

// round 3
// speedup vs baseline: 1.5640x; 1.2632x over previous
#include <cuda_runtime.h>

#define W 224
#define WW (W * W)                  // 50176
#define F4_PER (WW / 4)             // 12544 float4 per sample
#define F4_PER_ROW (W / 4)          // 56
#define NSAMP 256
#define F4_TOTAL (NSAMP * F4_PER)   // 3,211,264
#define BLK_PER_SAMP 7
#define NBLK1 (NSAMP * BLK_PER_SAMP)      // 1792
#define F4_PER_BLK (F4_PER / BLK_PER_SAMP) // 1792 = 256 thr * 7 f4

// Scratch (device globals; zero-initialized at load, re-zeroed by k_xy each call)
__device__ unsigned g_maxbits[NSAMP];     // atomicMax of float bits (values >= 0)
__device__ int4     g_blk[NBLK1];         // per-block {maxbits, cnt, si, sj}
__device__ float2   g_xy[NSAMP];
__device__ double   g_acc;

// ---------------------------------------------------------------------------
// Kernel 1: per-block max + tie stats in ONE pass (ties counted from registers).
// grid = 1792 (7 blocks/sample), 256 threads, 7 float4 per thread.
// ---------------------------------------------------------------------------
__global__ __launch_bounds__(256) void k_maxstats(const float* __restrict__ tgt) {
    const int b = blockIdx.x / BLK_PER_SAMP;
    const int c = blockIdx.x - b * BLK_PER_SAMP;
    const int tid = threadIdx.x;
    const float4* __restrict__ t4 =
        reinterpret_cast<const float4*>(tgt) + (size_t)b * F4_PER + c * F4_PER_BLK;

    // Front-batched loads into registers (MLP = 7)
    float4 v[7];
    #pragma unroll
    for (int k = 0; k < 7; k++) v[k] = t4[k * 256 + tid];

    // Thread max, branch-free
    float tmax = -3.0e38f;
    #pragma unroll
    for (int k = 0; k < 7; k++)
        tmax = fmaxf(tmax, fmaxf(fmaxf(v[k].x, v[k].y), fmaxf(v[k].z, v[k].w)));

    // Block max
    float m = tmax;
    #pragma unroll
    for (int o = 16; o > 0; o >>= 1)
        m = fmaxf(m, __shfl_xor_sync(0xffffffffu, m, o));

    __shared__ float smax[8];
    __shared__ float sM;
    __shared__ int scnt, ssi, ssj;
    const int wid = tid >> 5, lid = tid & 31;
    if (lid == 0) smax[wid] = m;
    if (tid == 0) { scnt = 0; ssi = 0; ssj = 0; }
    __syncthreads();
    if (tid == 0) {
        float bm = smax[0];
        #pragma unroll
        for (int w = 1; w < 8; w++) bm = fmaxf(bm, smax[w]);
        sM = bm;
    }
    __syncthreads();
    const float M = sM;

    // Tie stats from registers — only threads holding the block max participate
    if (tmax == M) {
        int cnt = 0, si = 0, sj = 0;
        #pragma unroll
        for (int k = 0; k < 7; k++) {
            const int r4 = c * F4_PER_BLK + k * 256 + tid;  // f4 idx within sample
            const int i  = r4 / F4_PER_ROW;
            const int j0 = (r4 - i * F4_PER_ROW) * 4;
            if (v[k].x == M) { cnt++; si += i; sj += j0;     }
            if (v[k].y == M) { cnt++; si += i; sj += j0 + 1; }
            if (v[k].z == M) { cnt++; si += i; sj += j0 + 2; }
            if (v[k].w == M) { cnt++; si += i; sj += j0 + 3; }
        }
        atomicAdd_block(&scnt, cnt);
        atomicAdd_block(&ssi,  si);
        atomicAdd_block(&ssj,  sj);
    }
    __syncthreads();

    if (tid == 0) {
        const unsigned mb = __float_as_uint(M);   // M >= 0 -> bit order == float order
        g_blk[blockIdx.x] = make_int4((int)mb, scnt, ssi, ssj);
        atomicMax(&g_maxbits[b], mb);
    }
}

// ---------------------------------------------------------------------------
// Kernel 2 (tiny): combine per-block entries -> centroid; reset atomics.
// ---------------------------------------------------------------------------
__global__ void k_xy() {
    const int b = threadIdx.x;                    // 256 threads, one per sample
    const unsigned Mb = g_maxbits[b];
    int cnt = 0, si = 0, sj = 0;
    #pragma unroll
    for (int c = 0; c < BLK_PER_SAMP; c++) {
        int4 e = g_blk[b * BLK_PER_SAMP + c];
        if ((unsigned)e.x == Mb) { cnt += e.y; si += e.z; sj += e.w; }
    }
    const float inv = 1.0f / (float)cnt;
    g_xy[b] = make_float2((float)si * inv, (float)sj * inv);
    g_maxbits[b] = 0u;                            // reset for next graph replay
    if (b == 0) g_acc = 0.0;
}

// ---------------------------------------------------------------------------
// Kernel 3: weighted BCE partial sums. input via __ldcs (evict-first) so the
// L2-resident target from k_maxstats survives.
// ---------------------------------------------------------------------------
__global__ __launch_bounds__(256) void k_loss(const float* __restrict__ inp,
                                              const float* __restrict__ tgt) {
    const float4* __restrict__ p4 = reinterpret_cast<const float4*>(inp);
    const float4* __restrict__ t4 = reinterpret_cast<const float4*>(tgt);

    float s = 0.0f;
    #pragma unroll
    for (int k = 0; k < 4; k++) {
        const int p = blockIdx.x * 1024 + k * 256 + threadIdx.x;   // global f4 idx
        float4 pv = __ldcs(p4 + p);        // streaming: don't pollute L2
        float4 tv = t4[p];                 // expect L2 hit

        const int b = p / F4_PER;
        const int r = p - b * F4_PER;
        const int i  = r / F4_PER_ROW;
        const int j0 = (r - i * F4_PER_ROW) * 4;

        const float2 xy = g_xy[b];
        const float di  = (float)i - xy.x;
        const float di2 = di * di;

        float pe[4] = {pv.x, pv.y, pv.z, pv.w};
        float te[4] = {tv.x, tv.y, tv.z, tv.w};
        #pragma unroll
        for (int e = 0; e < 4; e++) {
            float dj  = (float)(j0 + e) - xy.y;
            float wgt = __fdividef((float)W, sqrtf(fmaf(dj, dj, di2)) + 1.0f);
            float lp  = fmaxf(__logf(pe[e]),        -100.0f);
            float lq  = fmaxf(__logf(1.0f - pe[e]), -100.0f);
            s += wgt * (-(te[e] * lp + (1.0f - te[e]) * lq));
        }
    }

    #pragma unroll
    for (int o = 16; o > 0; o >>= 1)
        s += __shfl_xor_sync(0xffffffffu, s, o);

    __shared__ float sw[8];
    const int wid = threadIdx.x >> 5, lid = threadIdx.x & 31;
    if (lid == 0) sw[wid] = s;
    __syncthreads();
    if (threadIdx.x == 0) {
        float bs = sw[0];
        #pragma unroll
        for (int w = 1; w < 8; w++) bs += sw[w];
        atomicAdd(&g_acc, (double)bs);
    }
}

// ---------------------------------------------------------------------------
// Kernel 4: finalize mean.
// ---------------------------------------------------------------------------
__global__ void k_final(float* __restrict__ out, double invn) {
    out[0] = (float)(g_acc * invn);
}

extern "C" void kernel_launch(void* const* d_in, const int* in_sizes, int n_in,
                              void* d_out, int out_size) {
    const float* inp = (const float*)d_in[0];
    const float* tgt = (const float*)d_in[1];
    float* out = (float*)d_out;

    k_maxstats<<<NBLK1, 256>>>(tgt);
    k_xy<<<1, NSAMP>>>();
    k_loss<<<F4_TOTAL / 1024, 256>>>(inp, tgt);
    k_final<<<1, 1>>>(out, 1.0 / (double)((size_t)NSAMP * WW));
}